// round 7
// baseline (speedup 1.0000x reference)
#include <cuda_runtime.h>

// ---------------------------------------------------------------------------
// GATNet: 2-layer GAT, N=50000, E=800000 (+N self loops).
// R6 -> R7: REVERT to the proven R5 scatter structure (409us), then:
//  (1) transposed weights (W1t/W2t) so GEMM threads do float4 loads,
//  (2) (src,dst) packed into one int2 array (half the index loads),
//  (3) launch order places k_gemm1 at the ncu capture slot (index 3).
// ---------------------------------------------------------------------------

#define N_NODES 50000
#define F_IN    128
#define HID     64
#define C_OUT   121
#define C_PAD   124                       // 31 float4 chunks
#define E_RAW   800000
#define E_TOT   (E_RAW + N_NODES)

// Scratch (static device globals -- allocation is forbidden)
__device__ __align__(8)  int2  g_sd[E_RAW];               // packed (src,dst)
__device__ int   g_is32;
__device__ __align__(16) float g_h1  [N_NODES * HID];     // x @ W1
__device__ __align__(16) float g_acc1[N_NODES * HID];     // layer1 aggregation
__device__ __align__(16) float g_hW2 [N_NODES * C_PAD];   // relu(acc1+b1)@W2, padded
__device__ __align__(16) float g_acc2[N_NODES * C_PAD];   // layer2 aggregation, padded
__device__ float g_as [N_NODES];
__device__ float g_ad [N_NODES];
__device__ float g_e  [E_TOT];
__device__ float g_d  [N_NODES];
__device__ __align__(16) float g_W1t[HID * F_IN];         // W1^T [64][128]
__device__ __align__(16) float g_W2t[C_OUT * HID];        // W2^T [121][64]

__device__ __forceinline__ void red_add_v4(float* addr, float4 v) {
    asm volatile("red.global.add.v4.f32 [%0], {%1,%2,%3,%4};"
                 :: "l"(addr), "f"(v.x), "f"(v.y), "f"(v.z), "f"(v.w)
                 : "memory");
}

// ---------------- dtype detection + index conversion -----------------------
// int64 ids < 2^31 -> every odd 32-bit word is 0; int32 -> random ids.
__global__ void k_detect(const unsigned* __restrict__ ei32) {
    __shared__ int found;
    if (threadIdx.x == 0) found = 0;
    __syncthreads();
    int local = 0;
    for (int k = threadIdx.x; k < 4096; k += blockDim.x) {
        const int j = k * (E_RAW / 4096);
        if (ei32[2 * j + 1] != 0u) local = 1;
    }
    if (local) found = 1;
    __syncthreads();
    if (threadIdx.x == 0) g_is32 = found;
}

__global__ void k_convert(const void* __restrict__ ei) {
    const int i = blockIdx.x * blockDim.x + threadIdx.x;
    if (i >= E_RAW) return;
    int s, d;
    if (g_is32) {
        s = ((const int*)ei)[i];
        d = ((const int*)ei)[E_RAW + i];
    } else {
        s = (int)((const long long*)ei)[i];
        d = (int)((const long long*)ei)[E_RAW + i];
    }
    g_sd[i] = make_int2(s, d);
}

// ---------------- weight transposes ----------------------------------------
__global__ void k_wtrans(const float* __restrict__ W1,
                         const float* __restrict__ W2) {
    const int stride = gridDim.x * blockDim.x;
    const int i0 = blockIdx.x * blockDim.x + threadIdx.x;
    for (int t = i0; t < HID * F_IN; t += stride) {
        const int f = t / F_IN, k = t - f * F_IN;
        g_W1t[f * F_IN + k] = W1[k * HID + f];
    }
    for (int t = i0; t < C_OUT * HID; t += stride) {
        const int f = t / HID, k = t - f * HID;
        g_W2t[f * HID + k] = W2[k * C_OUT + f];
    }
}

// ---------------- GEMM 1: h1 = x @ W1t, alpha_src/dst ----------------------
__global__ void k_gemm1(const float* __restrict__ x,
                        const float* __restrict__ a_src,
                        const float* __restrict__ a_dst) {
    __shared__ __align__(16) float4 xs4[F_IN / 4];
    __shared__ float r1[HID], r2[HID];
    const int node = blockIdx.x;
    const int f = threadIdx.x;  // 0..63
    if (f < F_IN / 4) xs4[f] = ((const float4*)x)[node * (F_IN / 4) + f];
    __syncthreads();
    const float4* w4 = (const float4*)(g_W1t + f * F_IN);
    float acc = 0.f;
#pragma unroll
    for (int j = 0; j < F_IN / 4; j++) {
        const float4 w = w4[j];
        const float4 v = xs4[j];
        acc += w.x * v.x + w.y * v.y + w.z * v.z + w.w * v.w;
    }
    g_h1[node * HID + f] = acc;
    r1[f] = acc * a_src[f];
    r2[f] = acc * a_dst[f];
    __syncthreads();
    for (int s = HID / 2; s > 0; s >>= 1) {
        if (f < s) { r1[f] += r1[f + s]; r2[f] += r2[f + s]; }
        __syncthreads();
    }
    if (f == 0) { g_as[node] = r1[0]; g_ad[node] = r2[0]; }
}

// ---------------- init: zero accumulators + denominators (float4) ----------
__global__ void k_init1() {
    const int stride = gridDim.x * blockDim.x;
    const int i0 = blockIdx.x * blockDim.x + threadIdx.x;
    float4* a = (float4*)g_acc1;
    const float4 z = make_float4(0.f, 0.f, 0.f, 0.f);
    for (int t = i0; t < N_NODES * HID / 4; t += stride) a[t] = z;
    for (int t = i0; t < N_NODES; t += stride) g_d[t] = 0.f;
}
__global__ void k_init2() {
    const int stride = gridDim.x * blockDim.x;
    const int i0 = blockIdx.x * blockDim.x + threadIdx.x;
    float4* a = (float4*)g_acc2;
    const float4 z = make_float4(0.f, 0.f, 0.f, 0.f);
    for (int t = i0; t < N_NODES * C_PAD / 4; t += stride) a[t] = z;
    for (int t = i0; t < N_NODES; t += stride) g_d[t] = 0.f;
}

// ---------------- edge pass A: w = exp(leaky(as+ad)); denom += w -----------
__global__ void k_edge_exp() {
    const int i = blockIdx.x * blockDim.x + threadIdx.x;
    if (i >= E_TOT) return;
    int s, d;
    if (i < E_RAW) { const int2 sd = g_sd[i]; s = sd.x; d = sd.y; }
    else           { s = d = i - E_RAW; }
    float e = g_as[s] + g_ad[d];
    e = (e > 0.f) ? e : 0.2f * e;       // leaky_relu, NEG_SLOPE=0.2
    const float w = __expf(e);
    g_e[i] = w;
    atomicAdd(&g_d[d], w);
}

// ---------------- edge pass A2: normalize attention ------------------------
__global__ void k_edge_norm() {
    const int i = blockIdx.x * blockDim.x + threadIdx.x;
    if (i >= E_TOT) return;
    const int d = (i < E_RAW) ? g_sd[i].y : (i - E_RAW);
    g_e[i] = g_e[i] / g_d[d];
}

// ---------------- edge pass B: weighted feature scatter (float4) -----------
// Layer 1: 64 feats = 16 float4 chunks; 16 threads per edge.
__global__ void k_scatter1() {
    const unsigned t = blockIdx.x * blockDim.x + threadIdx.x;
    if (t >= (unsigned)E_TOT * 16) return;
    const unsigned i = t >> 4;
    const unsigned c = t & 15u;
    int s, d;
    if (i < E_RAW) { const int2 sd = g_sd[i]; s = sd.x; d = sd.y; }
    else           { s = d = (int)(i - E_RAW); }
    const float att = g_e[i];
    float4 h = *(const float4*)(g_h1 + s * HID + c * 4);
    h.x *= att; h.y *= att; h.z *= att; h.w *= att;
    red_add_v4(g_acc1 + d * HID + c * 4, h);
}

// Layer 2: 124 padded feats = 31 float4 chunks; 32 threads/edge, lane 31 idle.
__global__ void k_scatter2() {
    const unsigned t = blockIdx.x * blockDim.x + threadIdx.x;
    const unsigned c = t & 31u;
    if (c >= 31u) return;
    if (t >= (unsigned)E_TOT * 32) return;
    const unsigned i = t >> 5;
    int s, d;
    if (i < E_RAW) { const int2 sd = g_sd[i]; s = sd.x; d = sd.y; }
    else           { s = d = (int)(i - E_RAW); }
    const float att = g_e[i];
    float4 h = *(const float4*)(g_hW2 + s * C_PAD + c * 4);
    h.x *= att; h.y *= att; h.z *= att; h.w *= att;
    red_add_v4(g_acc2 + d * C_PAD + c * 4, h);
}

// ---------------- GEMM 2: hW2 = relu(acc1+b1) @ W2t, alpha2 ----------------
__global__ void k_gemm2(const float* __restrict__ b1,
                        const float* __restrict__ a_src2,
                        const float* __restrict__ a_dst2) {
    __shared__ __align__(16) float hs[HID];
    __shared__ float r1[128], r2[128];
    const int node = blockIdx.x;
    const int f = threadIdx.x;  // 0..127
    if (f < HID) {
        float v = g_acc1[node * HID + f] + b1[f];
        hs[f] = (v > 0.f) ? v : 0.f;
    }
    __syncthreads();
    if (f < C_OUT) {
        const float4* w4 = (const float4*)(g_W2t + f * HID);
        const float4* v4 = (const float4*)hs;
        float acc = 0.f;
#pragma unroll
        for (int j = 0; j < HID / 4; j++) {
            const float4 w = w4[j];
            const float4 v = v4[j];
            acc += w.x * v.x + w.y * v.y + w.z * v.z + w.w * v.w;
        }
        g_hW2[node * C_PAD + f] = acc;
        r1[f] = acc * a_src2[f];
        r2[f] = acc * a_dst2[f];
    } else {
        if (f < C_PAD) g_hW2[node * C_PAD + f] = 0.f;   // zero padding cols
        r1[f] = 0.f; r2[f] = 0.f;
    }
    __syncthreads();
    for (int s = 64; s > 0; s >>= 1) {
        if (f < s) { r1[f] += r1[f + s]; r2[f] += r2[f + s]; }
        __syncthreads();
    }
    if (f == 0) { g_as[node] = r1[0]; g_ad[node] = r2[0]; }
}

// ---------------- finalize: out = sigmoid(acc2 + b2) -----------------------
__global__ void k_final(float* __restrict__ out, const float* __restrict__ b2) {
    const int t = blockIdx.x * blockDim.x + threadIdx.x;
    if (t >= N_NODES * C_OUT) return;
    const int d = t / C_OUT;
    const int f = t - d * C_OUT;
    const float v = g_acc2[d * C_PAD + f] + b2[f];
    out[t] = 1.f / (1.f + __expf(-v));
}

// ---------------------------------------------------------------------------
extern "C" void kernel_launch(void* const* d_in, const int* in_sizes, int n_in,
                              void* d_out, int out_size) {
    const float* x      = (const float*)d_in[0];
    const void*  ei     = d_in[1];
    const float* W1     = (const float*)d_in[2];
    const float* a_src1 = (const float*)d_in[3];
    const float* a_dst1 = (const float*)d_in[4];
    const float* b1     = (const float*)d_in[5];
    const float* W2     = (const float*)d_in[6];
    const float* a_src2 = (const float*)d_in[7];
    const float* a_dst2 = (const float*)d_in[8];
    const float* b2     = (const float*)d_in[9];
    float*       out    = (float*)d_out;

    const int TPB = 256;
    const int gE  = (E_RAW + TPB - 1) / TPB;
    const int gET = (E_TOT + TPB - 1) / TPB;

    // Launch order places k_gemm1 at capture index 3 (ncu lands there).
    k_detect<<<1, 256>>>((const unsigned*)ei);          // 0
    k_convert<<<gE, TPB>>>(ei);                         // 1
    k_wtrans<<<32, TPB>>>(W1, W2);                      // 2

    // ----- Layer 1 -----
    k_gemm1<<<N_NODES, HID>>>(x, a_src1, a_dst1);       // 3  <- profiled
    k_init1<<<512, TPB>>>();                            // 4
    k_edge_exp<<<gET, TPB>>>();                         // 5
    k_edge_norm<<<gET, TPB>>>();                        // 6
    {
        const unsigned work = (unsigned)E_TOT * 16;
        k_scatter1<<<(work + TPB - 1) / TPB, TPB>>>();  // 7
    }

    // ----- Layer 2 -----
    k_gemm2<<<N_NODES, 128>>>(b1, a_src2, a_dst2);      // 8
    k_init2<<<512, TPB>>>();                            // 9
    k_edge_exp<<<gET, TPB>>>();                         // 10
    k_edge_norm<<<gET, TPB>>>();                        // 11
    {
        const unsigned work = (unsigned)E_TOT * 32;
        k_scatter2<<<(work + TPB - 1) / TPB, TPB>>>();  // 12
    }

    // ----- Output -----
    {
        const int total = N_NODES * C_OUT;
        k_final<<<(total + TPB - 1) / TPB, TPB>>>(out, b2);  // 13
    }
}

// round 10
// speedup vs baseline: 3.5177x; 3.5177x over previous
#include <cuda_runtime.h>

// ---------------------------------------------------------------------------
// GATNet: 2-layer GAT, N=50000, E=800000 (+N self loops).
// R9 resubmit (R9 was a broker/container infra failure; kernel never ran):
// tiled shared-memory GEMMs (coalesced tile loads, register blocking
// 4 nodes x 4/8 feats, shfl alpha reductions) + the proven R5 float4
// scatter path with int2-packed indices. C_PAD=128: scatter2 all lanes.
// ---------------------------------------------------------------------------

#define N_NODES 50000
#define F_IN    128
#define HID     64
#define C_OUT   121
#define C_PAD   128                       // 32 float4 chunks
#define E_RAW   800000
#define E_TOT   (E_RAW + N_NODES)
#define NB      ((N_NODES + 63) / 64)     // 782 node-tile blocks

// Scratch (static device globals -- allocation is forbidden)
__device__ __align__(8)  int2  g_sd[E_RAW];               // packed (src,dst)
__device__ int   g_is32;
__device__ __align__(16) float g_h1  [N_NODES * HID];     // x @ W1
__device__ __align__(16) float g_acc1[N_NODES * HID];     // layer1 aggregation
__device__ __align__(16) float g_hW2 [N_NODES * C_PAD];   // relu(acc1+b1)@W2, padded
__device__ __align__(16) float g_acc2[N_NODES * C_PAD];   // layer2 aggregation
__device__ float g_as [N_NODES];
__device__ float g_ad [N_NODES];
__device__ float g_e  [E_TOT];
__device__ float g_d  [N_NODES];

__device__ __forceinline__ void red_add_v4(float* addr, float4 v) {
    asm volatile("red.global.add.v4.f32 [%0], {%1,%2,%3,%4};"
                 :: "l"(addr), "f"(v.x), "f"(v.y), "f"(v.z), "f"(v.w)
                 : "memory");
}

// ---------------- dtype detection -------------------------------------------
// int64 ids < 2^31 -> every odd 32-bit word is 0; int32 -> random ids.
__global__ void k_detect(const unsigned* __restrict__ ei32) {
    __shared__ int found;
    if (threadIdx.x == 0) found = 0;
    __syncthreads();
    int local = 0;
    for (int k = threadIdx.x; k < 4096; k += blockDim.x) {
        const int j = k * (E_RAW / 4096);
        if (ei32[2 * j + 1] != 0u) local = 1;
    }
    if (local) found = 1;
    __syncthreads();
    if (threadIdx.x == 0) g_is32 = found;
}

// ---------------- convert indices + zero layer-1 state ----------------------
__global__ void k_convert_init(const void* __restrict__ ei) {
    const int stride = gridDim.x * blockDim.x;
    const int i0 = blockIdx.x * blockDim.x + threadIdx.x;
    for (int i = i0; i < E_RAW; i += stride) {
        int s, d;
        if (g_is32) {
            s = ((const int*)ei)[i];
            d = ((const int*)ei)[E_RAW + i];
        } else {
            s = (int)((const long long*)ei)[i];
            d = (int)((const long long*)ei)[E_RAW + i];
        }
        g_sd[i] = make_int2(s, d);
    }
    float4* a = (float4*)g_acc1;
    const float4 z = make_float4(0.f, 0.f, 0.f, 0.f);
    for (int t = i0; t < N_NODES * HID / 4; t += stride) a[t] = z;
    for (int t = i0; t < N_NODES; t += stride) g_d[t] = 0.f;
}

// ---------------- GEMM 1 (tiled): h1 = x @ W1, alphas -----------------------
// 64 nodes/block, 256 threads; thread = 4 nodes x 4 feats.
__global__ void k_gemm1(const float* __restrict__ x,
                        const float* __restrict__ W1,
                        const float* __restrict__ a_src,
                        const float* __restrict__ a_dst) {
    __shared__ float xs[64 * 33];          // [node][kk] padded (33)
    __shared__ float ws[32 * 64];          // [kk][f]
    const int tid = threadIdx.x;
    const int n0  = blockIdx.x * 64;
    const int nb  = tid >> 4;              // node group: nodes nb*4..nb*4+3
    const int fg  = tid & 15;              // feat group: f = fg*4..fg*4+3
    float4 acc[4];
    acc[0] = acc[1] = acc[2] = acc[3] = make_float4(0.f, 0.f, 0.f, 0.f);

    for (int kt = 0; kt < 4; kt++) {
        __syncthreads();
        for (int l = tid; l < 64 * 32; l += 256) {
            const int row = l >> 5, col = l & 31;
            const int node = n0 + row;
            xs[row * 33 + col] = (node < N_NODES)
                ? x[node * F_IN + kt * 32 + col] : 0.f;
        }
        for (int l = tid; l < 32 * 64; l += 256)
            ws[l] = W1[kt * 2048 + l];     // linear, coalesced
        __syncthreads();
#pragma unroll 8
        for (int kk = 0; kk < 32; kk++) {
            const float4 wv = *(const float4*)(ws + kk * 64 + fg * 4);
#pragma unroll
            for (int i = 0; i < 4; i++) {
                const float xv = xs[(nb * 4 + i) * 33 + kk];
                acc[i].x += xv * wv.x; acc[i].y += xv * wv.y;
                acc[i].z += xv * wv.z; acc[i].w += xv * wv.w;
            }
        }
    }

    const float4 s4 = *(const float4*)(a_src + fg * 4);
    const float4 d4 = *(const float4*)(a_dst + fg * 4);
    float ps[4], pd[4];
#pragma unroll
    for (int i = 0; i < 4; i++) {
        ps[i] = acc[i].x * s4.x + acc[i].y * s4.y + acc[i].z * s4.z + acc[i].w * s4.w;
        pd[i] = acc[i].x * d4.x + acc[i].y * d4.y + acc[i].z * d4.z + acc[i].w * d4.w;
    }
#pragma unroll
    for (int off = 8; off > 0; off >>= 1) {
#pragma unroll
        for (int i = 0; i < 4; i++) {
            ps[i] += __shfl_down_sync(0xffffffffu, ps[i], off, 16);
            pd[i] += __shfl_down_sync(0xffffffffu, pd[i], off, 16);
        }
    }
#pragma unroll
    for (int i = 0; i < 4; i++) {
        const int node = n0 + nb * 4 + i;
        if (node < N_NODES) {
            *(float4*)(g_h1 + node * HID + fg * 4) = acc[i];
            if (fg == 0) { g_as[node] = ps[i]; g_ad[node] = pd[i]; }
        }
    }
}

// ---------------- edge pass A: w = exp(leaky(as+ad)); denom += w -----------
__global__ void k_edge_exp() {
    const int i = blockIdx.x * blockDim.x + threadIdx.x;
    if (i >= E_TOT) return;
    int s, d;
    if (i < E_RAW) { const int2 sd = g_sd[i]; s = sd.x; d = sd.y; }
    else           { s = d = i - E_RAW; }
    float e = g_as[s] + g_ad[d];
    e = (e > 0.f) ? e : 0.2f * e;       // leaky_relu, NEG_SLOPE=0.2
    const float w = __expf(e);
    g_e[i] = w;
    atomicAdd(&g_d[d], w);
}

// ---------------- edge pass A2: normalize attention ------------------------
__global__ void k_edge_norm() {
    const int i = blockIdx.x * blockDim.x + threadIdx.x;
    if (i >= E_TOT) return;
    const int d = (i < E_RAW) ? g_sd[i].y : (i - E_RAW);
    g_e[i] = g_e[i] / g_d[d];
}

// ---------------- scatter, layer 1: 16 threads/edge (float4) ---------------
__global__ void k_scatter1() {
    const unsigned t = blockIdx.x * blockDim.x + threadIdx.x;
    if (t >= (unsigned)E_TOT * 16) return;
    const unsigned i = t >> 4;
    const unsigned c = t & 15u;
    int s, d;
    if (i < E_RAW) { const int2 sd = g_sd[i]; s = sd.x; d = sd.y; }
    else           { s = d = (int)(i - E_RAW); }
    const float att = g_e[i];
    float4 h = *(const float4*)(g_h1 + s * HID + c * 4);
    h.x *= att; h.y *= att; h.z *= att; h.w *= att;
    red_add_v4(g_acc1 + d * HID + c * 4, h);
}

// ---------------- scatter, layer 2: 32 threads/edge (float4, all active) ---
__global__ void k_scatter2() {
    const unsigned t = blockIdx.x * blockDim.x + threadIdx.x;
    if (t >= (unsigned)E_TOT * 32) return;
    const unsigned i = t >> 5;
    const unsigned c = t & 31u;
    int s, d;
    if (i < E_RAW) { const int2 sd = g_sd[i]; s = sd.x; d = sd.y; }
    else           { s = d = (int)(i - E_RAW); }
    const float att = g_e[i];
    float4 h = *(const float4*)(g_hW2 + s * C_PAD + c * 4);
    h.x *= att; h.y *= att; h.z *= att; h.w *= att;
    red_add_v4(g_acc2 + d * C_PAD + c * 4, h);
}

// ---------------- GEMM 2 (tiled): hW2 = relu(acc1+b1) @ W2, alphas ---------
// 64 nodes/block, 256 threads; thread = 4 nodes x 8 feats. smem = 48KB.
__global__ void k_gemm2(const float* __restrict__ W2,
                        const float* __restrict__ b1,
                        const float* __restrict__ a_src2,
                        const float* __restrict__ a_dst2) {
    __shared__ float hs [64 * 64];         // [node][k]
    __shared__ float ws2[64 * 128];        // [k][f] zero-padded f>=121
    const int tid = threadIdx.x;
    const int n0  = blockIdx.x * 64;
    const int nb  = tid >> 4;              // nodes nb*4..+3
    const int fg  = tid & 15;              // feats fg*8..+7
    for (int l = tid; l < 64 * 64; l += 256) {
        const int node = n0 + (l >> 6);
        const int k = l & 63;
        float v = (node < N_NODES) ? g_acc1[node * HID + k] + b1[k] : 0.f;
        hs[l] = (v > 0.f) ? v : 0.f;
    }
    for (int l = tid; l < 64 * 128; l += 256) {
        const int k = l >> 7, f = l & 127;
        ws2[l] = (f < C_OUT) ? W2[k * C_OUT + f] : 0.f;
    }
    __syncthreads();

    float4 acc[4][2];
#pragma unroll
    for (int i = 0; i < 4; i++) {
        acc[i][0] = make_float4(0.f, 0.f, 0.f, 0.f);
        acc[i][1] = make_float4(0.f, 0.f, 0.f, 0.f);
    }
#pragma unroll 4
    for (int kk = 0; kk < 64; kk++) {
        const float4 w0 = *(const float4*)(ws2 + kk * 128 + fg * 8);
        const float4 w1 = *(const float4*)(ws2 + kk * 128 + fg * 8 + 4);
#pragma unroll
        for (int i = 0; i < 4; i++) {
            const float xv = hs[(nb * 4 + i) * 64 + kk];
            acc[i][0].x += xv * w0.x; acc[i][0].y += xv * w0.y;
            acc[i][0].z += xv * w0.z; acc[i][0].w += xv * w0.w;
            acc[i][1].x += xv * w1.x; acc[i][1].y += xv * w1.y;
            acc[i][1].z += xv * w1.z; acc[i][1].w += xv * w1.w;
        }
    }

    float sa[8], da[8];
#pragma unroll
    for (int j = 0; j < 8; j++) {
        const int f = fg * 8 + j;
        sa[j] = (f < C_OUT) ? a_src2[f] : 0.f;
        da[j] = (f < C_OUT) ? a_dst2[f] : 0.f;
    }
    float ps[4], pd[4];
#pragma unroll
    for (int i = 0; i < 4; i++) {
        const float* a = (const float*)&acc[i][0];
        float s = 0.f, d = 0.f;
#pragma unroll
        for (int j = 0; j < 8; j++) { s += a[j] * sa[j]; d += a[j] * da[j]; }
        ps[i] = s; pd[i] = d;
    }
#pragma unroll
    for (int off = 8; off > 0; off >>= 1) {
#pragma unroll
        for (int i = 0; i < 4; i++) {
            ps[i] += __shfl_down_sync(0xffffffffu, ps[i], off, 16);
            pd[i] += __shfl_down_sync(0xffffffffu, pd[i], off, 16);
        }
    }
#pragma unroll
    for (int i = 0; i < 4; i++) {
        const int node = n0 + nb * 4 + i;
        if (node < N_NODES) {
            *(float4*)(g_hW2 + node * C_PAD + fg * 8)     = acc[i][0];
            *(float4*)(g_hW2 + node * C_PAD + fg * 8 + 4) = acc[i][1];
            if (fg == 0) { g_as[node] = ps[i]; g_ad[node] = pd[i]; }
        }
    }
}

// ---------------- init layer-2 state ---------------------------------------
__global__ void k_init2() {
    const int stride = gridDim.x * blockDim.x;
    const int i0 = blockIdx.x * blockDim.x + threadIdx.x;
    float4* a = (float4*)g_acc2;
    const float4 z = make_float4(0.f, 0.f, 0.f, 0.f);
    for (int t = i0; t < N_NODES * C_PAD / 4; t += stride) a[t] = z;
    for (int t = i0; t < N_NODES; t += stride) g_d[t] = 0.f;
}

// ---------------- finalize: out = sigmoid(acc2 + b2) -----------------------
__global__ void k_final(float* __restrict__ out, const float* __restrict__ b2) {
    const int t = blockIdx.x * blockDim.x + threadIdx.x;
    if (t >= N_NODES * C_OUT) return;
    const int d = t / C_OUT;
    const int f = t - d * C_OUT;
    const float v = g_acc2[d * C_PAD + f] + b2[f];
    out[t] = 1.f / (1.f + __expf(-v));
}

// ---------------------------------------------------------------------------
extern "C" void kernel_launch(void* const* d_in, const int* in_sizes, int n_in,
                              void* d_out, int out_size) {
    const float* x      = (const float*)d_in[0];
    const void*  ei     = d_in[1];
    const float* W1     = (const float*)d_in[2];
    const float* a_src1 = (const float*)d_in[3];
    const float* a_dst1 = (const float*)d_in[4];
    const float* b1     = (const float*)d_in[5];
    const float* W2     = (const float*)d_in[6];
    const float* a_src2 = (const float*)d_in[7];
    const float* a_dst2 = (const float*)d_in[8];
    const float* b2     = (const float*)d_in[9];
    float*       out    = (float*)d_out;

    const int TPB = 256;
    const int gET = (E_TOT + TPB - 1) / TPB;

    k_detect<<<1, 256>>>((const unsigned*)ei);               // 0
    k_convert_init<<<1024, TPB>>>(ei);                       // 1

    // ----- Layer 1 -----
    k_gemm1<<<NB, 256>>>(x, W1, a_src1, a_dst1);             // 2
    k_edge_exp<<<gET, TPB>>>();                              // 3  <- profiled
    k_edge_norm<<<gET, TPB>>>();                             // 4
    {
        const unsigned work = (unsigned)E_TOT * 16;
        k_scatter1<<<(work + TPB - 1) / TPB, TPB>>>();       // 5
    }

    // ----- Layer 2 -----
    k_gemm2<<<NB, 256>>>(W2, b1, a_src2, a_dst2);            // 6
    k_init2<<<512, TPB>>>();                                 // 7
    k_edge_exp<<<gET, TPB>>>();                              // 8
    k_edge_norm<<<gET, TPB>>>();                             // 9
    {
        const unsigned work = (unsigned)E_TOT * 32;
        k_scatter2<<<(work + TPB - 1) / TPB, TPB>>>();       // 10
    }

    // ----- Output -----
    {
        const int total = N_NODES * C_OUT;
        k_final<<<(total + TPB - 1) / TPB, TPB>>>(out, b2);  // 11
    }
}

// round 13
// speedup vs baseline: 4.0274x; 1.1449x over previous
#include <cuda_runtime.h>

// ---------------------------------------------------------------------------
// GATNet: 2-layer GAT, N=50000, E=800000 (+N self loops).
// R12 -> R13: R12 failed because __device__ globals were passed as kernel
// arguments FROM HOST code (host shadow-symbol address -> wild writes,
// caught by the harness memory checkpoint). Fixed: k_edge_exp / k_scatter
// take an int layer flag and resolve scratch pointers in device code.
// Design otherwise identical to R11:
//  (1) Layer 2 aggregates 64-dim relu features BEFORE W2 (linearity);
//      logits via precomputed v_s = W2 a_src2, v_d = W2 a_dst2.
//  (2) Softmax normalization deferred to node level; edge_norm deleted.
//  (3) All accumulators zeroed once in k_convert_init.
// ---------------------------------------------------------------------------

#define N_NODES 50000
#define F_IN    128
#define HID     64
#define C_OUT   121
#define E_RAW   800000
#define E_TOT   (E_RAW + N_NODES)
#define NB      ((N_NODES + 63) / 64)     // 782 node-tile blocks

// Scratch (static device globals -- allocation is forbidden)
__device__ __align__(8)  int2  g_sd[E_RAW];               // packed (src,dst)
__device__ int   g_is32;
__device__ __align__(16) float g_h1   [N_NODES * HID];    // x @ W1
__device__ __align__(16) float g_acc1 [N_NODES * HID];    // layer1 aggregation
__device__ __align__(16) float g_hrelu[N_NODES * HID];    // relu(acc1/d1 + b1)
__device__ __align__(16) float g_acc2 [N_NODES * HID];    // layer2 aggregation (64-dim)
__device__ float g_as[N_NODES];
__device__ float g_ad[N_NODES];
__device__ float g_e [E_TOT];
__device__ float g_d1[N_NODES];
__device__ float g_d2[N_NODES];
__device__ float g_vs[HID];                               // W2 @ a_src2
__device__ float g_vd[HID];                               // W2 @ a_dst2

__device__ __forceinline__ void red_add_v4(float* addr, float4 v) {
    asm volatile("red.global.add.v4.f32 [%0], {%1,%2,%3,%4};"
                 :: "l"(addr), "f"(v.x), "f"(v.y), "f"(v.z), "f"(v.w)
                 : "memory");
}

// ---------------- dtype detection -------------------------------------------
// int64 ids < 2^31 -> every odd 32-bit word is 0; int32 -> random ids.
__global__ void k_detect(const unsigned* __restrict__ ei32) {
    __shared__ int found;
    if (threadIdx.x == 0) found = 0;
    __syncthreads();
    int local = 0;
    for (int k = threadIdx.x; k < 4096; k += blockDim.x) {
        const int j = k * (E_RAW / 4096);
        if (ei32[2 * j + 1] != 0u) local = 1;
    }
    if (local) found = 1;
    __syncthreads();
    if (threadIdx.x == 0) g_is32 = found;
}

// ---------------- convert indices + zero all accumulators -------------------
__global__ void k_convert_init(const void* __restrict__ ei) {
    const int stride = gridDim.x * blockDim.x;
    const int i0 = blockIdx.x * blockDim.x + threadIdx.x;
    for (int i = i0; i < E_RAW; i += stride) {
        int s, d;
        if (g_is32) {
            s = ((const int*)ei)[i];
            d = ((const int*)ei)[E_RAW + i];
        } else {
            s = (int)((const long long*)ei)[i];
            d = (int)((const long long*)ei)[E_RAW + i];
        }
        g_sd[i] = make_int2(s, d);
    }
    const float4 z = make_float4(0.f, 0.f, 0.f, 0.f);
    float4* a1 = (float4*)g_acc1;
    float4* a2 = (float4*)g_acc2;
    for (int t = i0; t < N_NODES * HID / 4; t += stride) { a1[t] = z; a2[t] = z; }
    for (int t = i0; t < N_NODES; t += stride) { g_d1[t] = 0.f; g_d2[t] = 0.f; }
}

// ---------------- precompute v_s = W2 a_src2, v_d = W2 a_dst2 ---------------
__global__ void k_prep2(const float* __restrict__ W2,
                        const float* __restrict__ a_src2,
                        const float* __restrict__ a_dst2) {
    const int t = threadIdx.x;         // 0..127
    const int k = t & 63;
    const float* a = (t < 64) ? a_src2 : a_dst2;
    float acc = 0.f;
    for (int f = 0; f < C_OUT; f++) acc += W2[k * C_OUT + f] * a[f];
    if (t < 64) g_vs[k] = acc; else g_vd[k] = acc;
}

// ---------------- GEMM 1 (tiled): h1 = x @ W1, alphas -----------------------
// 64 nodes/block, 256 threads; thread = 4 nodes x 4 feats. (proven R10)
__global__ void k_gemm1(const float* __restrict__ x,
                        const float* __restrict__ W1,
                        const float* __restrict__ a_src,
                        const float* __restrict__ a_dst) {
    __shared__ float xs[64 * 33];          // [node][kk] padded (33)
    __shared__ float ws[32 * 64];          // [kk][f]
    const int tid = threadIdx.x;
    const int n0  = blockIdx.x * 64;
    const int nb  = tid >> 4;              // node group: nodes nb*4..nb*4+3
    const int fg  = tid & 15;              // feat group: f = fg*4..fg*4+3
    float4 acc[4];
    acc[0] = acc[1] = acc[2] = acc[3] = make_float4(0.f, 0.f, 0.f, 0.f);

    for (int kt = 0; kt < 4; kt++) {
        __syncthreads();
        for (int l = tid; l < 64 * 32; l += 256) {
            const int row = l >> 5, col = l & 31;
            const int node = n0 + row;
            xs[row * 33 + col] = (node < N_NODES)
                ? x[node * F_IN + kt * 32 + col] : 0.f;
        }
        for (int l = tid; l < 32 * 64; l += 256)
            ws[l] = W1[kt * 2048 + l];     // linear, coalesced
        __syncthreads();
#pragma unroll 8
        for (int kk = 0; kk < 32; kk++) {
            const float4 wv = *(const float4*)(ws + kk * 64 + fg * 4);
#pragma unroll
            for (int i = 0; i < 4; i++) {
                const float xv = xs[(nb * 4 + i) * 33 + kk];
                acc[i].x += xv * wv.x; acc[i].y += xv * wv.y;
                acc[i].z += xv * wv.z; acc[i].w += xv * wv.w;
            }
        }
    }

    const float4 s4 = *(const float4*)(a_src + fg * 4);
    const float4 d4 = *(const float4*)(a_dst + fg * 4);
    float ps[4], pd[4];
#pragma unroll
    for (int i = 0; i < 4; i++) {
        ps[i] = acc[i].x * s4.x + acc[i].y * s4.y + acc[i].z * s4.z + acc[i].w * s4.w;
        pd[i] = acc[i].x * d4.x + acc[i].y * d4.y + acc[i].z * d4.z + acc[i].w * d4.w;
    }
#pragma unroll
    for (int off = 8; off > 0; off >>= 1) {
#pragma unroll
        for (int i = 0; i < 4; i++) {
            ps[i] += __shfl_down_sync(0xffffffffu, ps[i], off, 16);
            pd[i] += __shfl_down_sync(0xffffffffu, pd[i], off, 16);
        }
    }
#pragma unroll
    for (int i = 0; i < 4; i++) {
        const int node = n0 + nb * 4 + i;
        if (node < N_NODES) {
            *(float4*)(g_h1 + node * HID + fg * 4) = acc[i];
            if (fg == 0) { g_as[node] = ps[i]; g_ad[node] = pd[i]; }
        }
    }
}

// ---------------- edge pass: w = exp(leaky(as+ad)); denom += w --------------
// layer flag selects denominator array IN DEVICE CODE (no host symbol use).
__global__ void k_edge_exp(int layer) {
    const int i = blockIdx.x * blockDim.x + threadIdx.x;
    if (i >= E_TOT) return;
    float* dnm = layer ? g_d2 : g_d1;
    int s, d;
    if (i < E_RAW) { const int2 sd = g_sd[i]; s = sd.x; d = sd.y; }
    else           { s = d = i - E_RAW; }
    float e = g_as[s] + g_ad[d];
    e = (e > 0.f) ? e : 0.2f * e;       // leaky_relu, NEG_SLOPE=0.2
    const float w = __expf(e);
    g_e[i] = w;
    atomicAdd(&dnm[d], w);
}

// ---------------- scatter: acc[d] += w * feat[s]  (64-dim, 16 lanes/edge) --
__global__ void k_scatter(int layer) {
    const unsigned t = blockIdx.x * blockDim.x + threadIdx.x;
    if (t >= (unsigned)E_TOT * 16) return;
    const float* feat = layer ? g_hrelu : g_h1;
    float*       acc  = layer ? g_acc2  : g_acc1;
    const unsigned i = t >> 4;
    const unsigned c = t & 15u;
    int s, d;
    if (i < E_RAW) { const int2 sd = g_sd[i]; s = sd.x; d = sd.y; }
    else           { s = d = (int)(i - E_RAW); }
    const float w = g_e[i];
    float4 h = *(const float4*)(feat + s * HID + c * 4);
    h.x *= w; h.y *= w; h.z *= w; h.w *= w;
    red_add_v4(acc + d * HID + c * 4, h);
}

// ---------------- node pass: hrelu = relu(acc1/d1 + b1); alphas2 ------------
// 1 warp per node, 2 feats per lane; 8 nodes per 256-thread block.
__global__ void k_hrelu(const float* __restrict__ b1) {
    const int node = blockIdx.x * 8 + (threadIdx.x >> 5);
    if (node >= N_NODES) return;
    const int lane = threadIdx.x & 31;
    const float inv = 1.f / g_d1[node];
    float2 a = ((const float2*)g_acc1)[node * (HID / 2) + lane];
    const float2 b = ((const float2*)b1)[lane];
    float hx = a.x * inv + b.x;
    float hy = a.y * inv + b.y;
    hx = hx > 0.f ? hx : 0.f;
    hy = hy > 0.f ? hy : 0.f;
    ((float2*)g_hrelu)[node * (HID / 2) + lane] = make_float2(hx, hy);
    const float2 vs = ((const float2*)g_vs)[lane];
    const float2 vd = ((const float2*)g_vd)[lane];
    float ps = hx * vs.x + hy * vs.y;
    float pd = hx * vd.x + hy * vd.y;
#pragma unroll
    for (int off = 16; off > 0; off >>= 1) {
        ps += __shfl_down_sync(0xffffffffu, ps, off);
        pd += __shfl_down_sync(0xffffffffu, pd, off);
    }
    if (lane == 0) { g_as[node] = ps; g_ad[node] = pd; }
}

// ---------------- output GEMM: out = sigmoid((acc2/d2) @ W2 + b2) -----------
// 64 nodes/block, 256 threads; thread = 4 nodes x 8 feats.
__global__ void k_out(const float* __restrict__ W2,
                      const float* __restrict__ b2,
                      float* __restrict__ out) {
    __shared__ float hs [64 * 64];         // [node][k] = acc2/d2
    __shared__ float ws2[64 * 128];        // [k][f] zero-padded f>=121
    const int tid = threadIdx.x;
    const int n0  = blockIdx.x * 64;
    const int nb  = tid >> 4;              // nodes nb*4..+3
    const int fg  = tid & 15;              // feats fg*8..+7
    for (int l = tid; l < 64 * 64; l += 256) {
        const int node = n0 + (l >> 6);
        const int k = l & 63;
        hs[l] = (node < N_NODES) ? g_acc2[node * HID + k] / g_d2[node] : 0.f;
    }
    for (int l = tid; l < 64 * 128; l += 256) {
        const int k = l >> 7, f = l & 127;
        ws2[l] = (f < C_OUT) ? W2[k * C_OUT + f] : 0.f;
    }
    __syncthreads();

    float4 acc[4][2];
#pragma unroll
    for (int i = 0; i < 4; i++) {
        acc[i][0] = make_float4(0.f, 0.f, 0.f, 0.f);
        acc[i][1] = make_float4(0.f, 0.f, 0.f, 0.f);
    }
#pragma unroll 4
    for (int kk = 0; kk < 64; kk++) {
        const float4 w0 = *(const float4*)(ws2 + kk * 128 + fg * 8);
        const float4 w1 = *(const float4*)(ws2 + kk * 128 + fg * 8 + 4);
#pragma unroll
        for (int i = 0; i < 4; i++) {
            const float xv = hs[(nb * 4 + i) * 64 + kk];
            acc[i][0].x += xv * w0.x; acc[i][0].y += xv * w0.y;
            acc[i][0].z += xv * w0.z; acc[i][0].w += xv * w0.w;
            acc[i][1].x += xv * w1.x; acc[i][1].y += xv * w1.y;
            acc[i][1].z += xv * w1.z; acc[i][1].w += xv * w1.w;
        }
    }

#pragma unroll
    for (int i = 0; i < 4; i++) {
        const int node = n0 + nb * 4 + i;
        if (node >= N_NODES) continue;
        const float* a = (const float*)&acc[i][0];
#pragma unroll
        for (int j = 0; j < 8; j++) {
            const int f = fg * 8 + j;
            if (f < C_OUT) {
                const float v = a[j] + b2[f];
                out[node * C_OUT + f] = 1.f / (1.f + __expf(-v));
            }
        }
    }
}

// ---------------------------------------------------------------------------
extern "C" void kernel_launch(void* const* d_in, const int* in_sizes, int n_in,
                              void* d_out, int out_size) {
    const float* x      = (const float*)d_in[0];
    const void*  ei     = d_in[1];
    const float* W1     = (const float*)d_in[2];
    const float* a_src1 = (const float*)d_in[3];
    const float* a_dst1 = (const float*)d_in[4];
    const float* b1     = (const float*)d_in[5];
    const float* W2     = (const float*)d_in[6];
    const float* a_src2 = (const float*)d_in[7];
    const float* a_dst2 = (const float*)d_in[8];
    const float* b2     = (const float*)d_in[9];
    float*       out    = (float*)d_out;

    const int TPB = 256;
    const int gET = (E_TOT + TPB - 1) / TPB;
    const unsigned scat_work = (unsigned)E_TOT * 16;
    const int gScat = (int)((scat_work + TPB - 1) / TPB);

    k_detect<<<1, 256>>>((const unsigned*)ei);               // 0
    k_convert_init<<<1024, TPB>>>(ei);                       // 1
    k_prep2<<<1, 128>>>(W2, a_src2, a_dst2);                 // 2

    // ----- Layer 1 -----
    k_gemm1<<<NB, 256>>>(x, W1, a_src1, a_dst1);             // 3  <- profiled
    k_edge_exp<<<gET, TPB>>>(0);                             // 4
    k_scatter<<<gScat, TPB>>>(0);                            // 5
    k_hrelu<<<(N_NODES + 7) / 8, TPB>>>(b1);                 // 6

    // ----- Layer 2 -----
    k_edge_exp<<<gET, TPB>>>(1);                             // 7
    k_scatter<<<gScat, TPB>>>(1);                            // 8

    // ----- Output GEMM + sigmoid -----
    k_out<<<NB, 256>>>(W2, b2, out);                         // 9
}

// round 14
// speedup vs baseline: 4.0697x; 1.0105x over previous
#include <cuda_runtime.h>

// ---------------------------------------------------------------------------
// GATNet: 2-layer GAT, N=50000, E=800000 (+N self loops).
// R13 -> R14:
//  (1) edge_exp fused INTO scatter: lane 0 of each 16-lane edge group
//      computes w=exp(leaky(as+ad)), does the denom atomic, shfl-broadcasts.
//      Both standalone edge passes and the g_e array deleted.
//  (2) gemm1 inner loop: float4 x loads (xs stride 36) -> 8 LDS.128 per
//      64 FFMA (was 20); k_out likewise (float4 hs loads).
//  (3) Launch order puts the fused scatter at ncu capture slot 3.
// Algebra unchanged from R13 (aggregate-then-project, deferred softmax norm).
// ---------------------------------------------------------------------------

#define N_NODES 50000
#define F_IN    128
#define HID     64
#define C_OUT   121
#define E_RAW   800000
#define E_TOT   (E_RAW + N_NODES)
#define NB      ((N_NODES + 63) / 64)     // 782 node-tile blocks

// Scratch (static device globals -- allocation is forbidden)
__device__ __align__(8)  int2  g_sd[E_RAW];               // packed (src,dst)
__device__ int   g_is32;
__device__ __align__(16) float g_h1   [N_NODES * HID];    // x @ W1
__device__ __align__(16) float g_acc1 [N_NODES * HID];    // layer1 aggregation
__device__ __align__(16) float g_hrelu[N_NODES * HID];    // relu(acc1/d1 + b1)
__device__ __align__(16) float g_acc2 [N_NODES * HID];    // layer2 aggregation (64-dim)
__device__ float g_as[N_NODES];
__device__ float g_ad[N_NODES];
__device__ float g_d1[N_NODES];
__device__ float g_d2[N_NODES];
__device__ float g_vs[HID];                               // W2 @ a_src2
__device__ float g_vd[HID];                               // W2 @ a_dst2

__device__ __forceinline__ void red_add_v4(float* addr, float4 v) {
    asm volatile("red.global.add.v4.f32 [%0], {%1,%2,%3,%4};"
                 :: "l"(addr), "f"(v.x), "f"(v.y), "f"(v.z), "f"(v.w)
                 : "memory");
}

// ---------------- dtype detection -------------------------------------------
// int64 ids < 2^31 -> every odd 32-bit word is 0; int32 -> random ids.
__global__ void k_detect(const unsigned* __restrict__ ei32) {
    __shared__ int found;
    if (threadIdx.x == 0) found = 0;
    __syncthreads();
    int local = 0;
    for (int k = threadIdx.x; k < 4096; k += blockDim.x) {
        const int j = k * (E_RAW / 4096);
        if (ei32[2 * j + 1] != 0u) local = 1;
    }
    if (local) found = 1;
    __syncthreads();
    if (threadIdx.x == 0) g_is32 = found;
}

// ---------------- convert indices + zero all accumulators -------------------
__global__ void k_convert_init(const void* __restrict__ ei) {
    const int stride = gridDim.x * blockDim.x;
    const int i0 = blockIdx.x * blockDim.x + threadIdx.x;
    for (int i = i0; i < E_RAW; i += stride) {
        int s, d;
        if (g_is32) {
            s = ((const int*)ei)[i];
            d = ((const int*)ei)[E_RAW + i];
        } else {
            s = (int)((const long long*)ei)[i];
            d = (int)((const long long*)ei)[E_RAW + i];
        }
        g_sd[i] = make_int2(s, d);
    }
    const float4 z = make_float4(0.f, 0.f, 0.f, 0.f);
    float4* a1 = (float4*)g_acc1;
    float4* a2 = (float4*)g_acc2;
    for (int t = i0; t < N_NODES * HID / 4; t += stride) { a1[t] = z; a2[t] = z; }
    for (int t = i0; t < N_NODES; t += stride) { g_d1[t] = 0.f; g_d2[t] = 0.f; }
}

// ---------------- precompute v_s = W2 a_src2, v_d = W2 a_dst2 ---------------
__global__ void k_prep2(const float* __restrict__ W2,
                        const float* __restrict__ a_src2,
                        const float* __restrict__ a_dst2) {
    const int t = threadIdx.x;         // 0..127
    const int k = t & 63;
    const float* a = (t < 64) ? a_src2 : a_dst2;
    float acc = 0.f;
    for (int f = 0; f < C_OUT; f++) acc += W2[k * C_OUT + f] * a[f];
    if (t < 64) g_vs[k] = acc; else g_vd[k] = acc;
}

// ---------------- GEMM 1 (tiled): h1 = x @ W1, alphas -----------------------
// 64 nodes/block, 256 threads; thread = 4 nodes x 4 feats.
// Inner loop uses float4 loads on BOTH operands (xs stride 36 for alignment).
__global__ void k_gemm1(const float* __restrict__ x,
                        const float* __restrict__ W1,
                        const float* __restrict__ a_src,
                        const float* __restrict__ a_dst) {
    __shared__ __align__(16) float xs[64 * 36];   // [node][kk], stride 36
    __shared__ __align__(16) float ws[32 * 64];   // [kk][f]
    const int tid = threadIdx.x;
    const int n0  = blockIdx.x * 64;
    const int nb  = tid >> 4;              // node group: nodes nb*4..nb*4+3
    const int fg  = tid & 15;              // feat group: f = fg*4..fg*4+3
    float4 acc[4];
    acc[0] = acc[1] = acc[2] = acc[3] = make_float4(0.f, 0.f, 0.f, 0.f);

    for (int kt = 0; kt < 4; kt++) {
        __syncthreads();
        for (int l = tid; l < 64 * 32; l += 256) {
            const int row = l >> 5, col = l & 31;
            const int node = n0 + row;
            xs[row * 36 + col] = (node < N_NODES)
                ? x[node * F_IN + kt * 32 + col] : 0.f;
        }
        for (int l = tid; l < 32 * 64; l += 256)
            ws[l] = W1[kt * 2048 + l];     // linear, coalesced
        __syncthreads();
#pragma unroll
        for (int kk = 0; kk < 32; kk += 4) {
            float4 xv[4];
#pragma unroll
            for (int i = 0; i < 4; i++)
                xv[i] = *(const float4*)(xs + (nb * 4 + i) * 36 + kk);
#pragma unroll
            for (int j = 0; j < 4; j++) {
                const float4 wv = *(const float4*)(ws + (kk + j) * 64 + fg * 4);
#pragma unroll
                for (int i = 0; i < 4; i++) {
                    const float xj = ((const float*)&xv[i])[j];
                    acc[i].x += xj * wv.x; acc[i].y += xj * wv.y;
                    acc[i].z += xj * wv.z; acc[i].w += xj * wv.w;
                }
            }
        }
    }

    const float4 s4 = *(const float4*)(a_src + fg * 4);
    const float4 d4 = *(const float4*)(a_dst + fg * 4);
    float ps[4], pd[4];
#pragma unroll
    for (int i = 0; i < 4; i++) {
        ps[i] = acc[i].x * s4.x + acc[i].y * s4.y + acc[i].z * s4.z + acc[i].w * s4.w;
        pd[i] = acc[i].x * d4.x + acc[i].y * d4.y + acc[i].z * d4.z + acc[i].w * d4.w;
    }
#pragma unroll
    for (int off = 8; off > 0; off >>= 1) {
#pragma unroll
        for (int i = 0; i < 4; i++) {
            ps[i] += __shfl_down_sync(0xffffffffu, ps[i], off, 16);
            pd[i] += __shfl_down_sync(0xffffffffu, pd[i], off, 16);
        }
    }
#pragma unroll
    for (int i = 0; i < 4; i++) {
        const int node = n0 + nb * 4 + i;
        if (node < N_NODES) {
            *(float4*)(g_h1 + node * HID + fg * 4) = acc[i];
            if (fg == 0) { g_as[node] = ps[i]; g_ad[node] = pd[i]; }
        }
    }
}

// ---------------- fused edge pass: w inline + denom atomic + scatter --------
// 16 lanes per edge. Lane 0 computes w = exp(leaky(as+ad)), adds to denom,
// shfl-broadcasts w to the group. E_TOT*16 is a multiple of 256: no partial
// warps, full-mask shfl is safe.
__global__ void k_scatter(int layer) {
    const unsigned t = blockIdx.x * blockDim.x + threadIdx.x;
    const float* feat = layer ? g_hrelu : g_h1;
    float*       acc  = layer ? g_acc2  : g_acc1;
    float*       dnm  = layer ? g_d2    : g_d1;
    const unsigned i = t >> 4;
    const unsigned c = t & 15u;
    int s, d;
    if (i < E_RAW) { const int2 sd = g_sd[i]; s = sd.x; d = sd.y; }
    else           { s = d = (int)(i - E_RAW); }
    float w = 0.f;
    if (c == 0) {
        float e = g_as[s] + g_ad[d];
        e = (e > 0.f) ? e : 0.2f * e;       // leaky_relu, NEG_SLOPE=0.2
        w = __expf(e);
        atomicAdd(&dnm[d], w);
    }
    w = __shfl_sync(0xffffffffu, w, 0, 16);
    float4 h = *(const float4*)(feat + s * HID + c * 4);
    h.x *= w; h.y *= w; h.z *= w; h.w *= w;
    red_add_v4(acc + d * HID + c * 4, h);
}

// ---------------- node pass: hrelu = relu(acc1/d1 + b1); alphas2 ------------
// 1 warp per node, 2 feats per lane; 8 nodes per 256-thread block.
__global__ void k_hrelu(const float* __restrict__ b1) {
    const int node = blockIdx.x * 8 + (threadIdx.x >> 5);
    if (node >= N_NODES) return;
    const int lane = threadIdx.x & 31;
    const float inv = 1.f / g_d1[node];
    float2 a = ((const float2*)g_acc1)[node * (HID / 2) + lane];
    const float2 b = ((const float2*)b1)[lane];
    float hx = a.x * inv + b.x;
    float hy = a.y * inv + b.y;
    hx = hx > 0.f ? hx : 0.f;
    hy = hy > 0.f ? hy : 0.f;
    ((float2*)g_hrelu)[node * (HID / 2) + lane] = make_float2(hx, hy);
    const float2 vs = ((const float2*)g_vs)[lane];
    const float2 vd = ((const float2*)g_vd)[lane];
    float ps = hx * vs.x + hy * vs.y;
    float pd = hx * vd.x + hy * vd.y;
#pragma unroll
    for (int off = 16; off > 0; off >>= 1) {
        ps += __shfl_down_sync(0xffffffffu, ps, off);
        pd += __shfl_down_sync(0xffffffffu, pd, off);
    }
    if (lane == 0) { g_as[node] = ps; g_ad[node] = pd; }
}

// ---------------- output GEMM: out = sigmoid((acc2/d2) @ W2 + b2) -----------
// 64 nodes/block, 256 threads; thread = 4 nodes x 8 feats. float4 hs loads.
__global__ void k_out(const float* __restrict__ W2,
                      const float* __restrict__ b2,
                      float* __restrict__ out) {
    __shared__ __align__(16) float hs [64 * 64];   // [node][k] = acc2/d2
    __shared__ __align__(16) float ws2[64 * 128];  // [k][f] zero-padded f>=121
    const int tid = threadIdx.x;
    const int n0  = blockIdx.x * 64;
    const int nb  = tid >> 4;              // nodes nb*4..+3
    const int fg  = tid & 15;              // feats fg*8..+7
    for (int l = tid; l < 64 * 64; l += 256) {
        const int node = n0 + (l >> 6);
        const int k = l & 63;
        hs[l] = (node < N_NODES) ? g_acc2[node * HID + k] / g_d2[node] : 0.f;
    }
    for (int l = tid; l < 64 * 128; l += 256) {
        const int k = l >> 7, f = l & 127;
        ws2[l] = (f < C_OUT) ? W2[k * C_OUT + f] : 0.f;
    }
    __syncthreads();

    float4 acc[4][2];
#pragma unroll
    for (int i = 0; i < 4; i++) {
        acc[i][0] = make_float4(0.f, 0.f, 0.f, 0.f);
        acc[i][1] = make_float4(0.f, 0.f, 0.f, 0.f);
    }
#pragma unroll
    for (int kk = 0; kk < 64; kk += 4) {
        float4 xv[4];
#pragma unroll
        for (int i = 0; i < 4; i++)
            xv[i] = *(const float4*)(hs + (nb * 4 + i) * 64 + kk);
#pragma unroll
        for (int j = 0; j < 4; j++) {
            const float4 w0 = *(const float4*)(ws2 + (kk + j) * 128 + fg * 8);
            const float4 w1 = *(const float4*)(ws2 + (kk + j) * 128 + fg * 8 + 4);
#pragma unroll
            for (int i = 0; i < 4; i++) {
                const float xj = ((const float*)&xv[i])[j];
                acc[i][0].x += xj * w0.x; acc[i][0].y += xj * w0.y;
                acc[i][0].z += xj * w0.z; acc[i][0].w += xj * w0.w;
                acc[i][1].x += xj * w1.x; acc[i][1].y += xj * w1.y;
                acc[i][1].z += xj * w1.z; acc[i][1].w += xj * w1.w;
            }
        }
    }

#pragma unroll
    for (int i = 0; i < 4; i++) {
        const int node = n0 + nb * 4 + i;
        if (node >= N_NODES) continue;
        const float* a = (const float*)&acc[i][0];
#pragma unroll
        for (int j = 0; j < 8; j++) {
            const int f = fg * 8 + j;
            if (f < C_OUT) {
                const float v = a[j] + b2[f];
                out[node * C_OUT + f] = 1.f / (1.f + __expf(-v));
            }
        }
    }
}

// ---------------------------------------------------------------------------
extern "C" void kernel_launch(void* const* d_in, const int* in_sizes, int n_in,
                              void* d_out, int out_size) {
    const float* x      = (const float*)d_in[0];
    const void*  ei     = d_in[1];
    const float* W1     = (const float*)d_in[2];
    const float* a_src1 = (const float*)d_in[3];
    const float* a_dst1 = (const float*)d_in[4];
    const float* b1     = (const float*)d_in[5];
    const float* W2     = (const float*)d_in[6];
    const float* a_src2 = (const float*)d_in[7];
    const float* a_dst2 = (const float*)d_in[8];
    const float* b2     = (const float*)d_in[9];
    float*       out    = (float*)d_out;

    const int TPB = 256;
    const unsigned scat_work = (unsigned)E_TOT * 16;       // 13,600,000
    const int gScat = (int)(scat_work / TPB);              // exact: 53125

    k_detect<<<1, 256>>>((const unsigned*)ei);               // 0
    k_convert_init<<<1024, TPB>>>(ei);                       // 1

    // ----- Layer 1 -----
    k_gemm1<<<NB, 256>>>(x, W1, a_src1, a_dst1);             // 2
    k_scatter<<<gScat, TPB>>>(0);                            // 3  <- profiled
    k_prep2<<<1, 128>>>(W2, a_src2, a_dst2);                 // 4
    k_hrelu<<<(N_NODES + 7) / 8, TPB>>>(b1);                 // 5

    // ----- Layer 2 -----
    k_scatter<<<gScat, TPB>>>(1);                            // 6

    // ----- Output GEMM + sigmoid -----
    k_out<<<NB, 256>>>(W2, b2, out);                         // 7
}